// round 8
// baseline (speedup 1.0000x reference)
#include <cuda_runtime.h>

// out[b, j1*64 + j2] = x[b, 0, j1] * x[b, 1, j2]
// x: [32768, 2, 64] f32, out: [32768, 4096] f32
// Persistent grid-stride kernel: 1184 CTAs (148 SM x 8), 256 threads each.
// Each iteration processes 2 batch rows with double-buffered SMEM input
// staging so the next rows' loads overlap the current rows' stores.

#define N_MF    64
#define ROW_IN  128   // 2 * 64 floats per batch row
#define ROW_OUT 4096
#define ROWS_PER_ITER 2
#define NUM_CTAS (148 * 8)

__global__ void __launch_bounds__(256, 8)
anfis_outer_persist_kernel(const float* __restrict__ x, float* __restrict__ out,
                           int n_iters) {
    const int tid = threadIdx.x;

    // double-buffered input staging: [buf][row][half][64]
    __shared__ float s[2][ROWS_PER_ITER][2][N_MF];

    const int row = tid >> 7;          // 0..1 (row within iter)
    const int off = tid & 127;         // 0..127

    // Prologue: load iteration 0's input.
    int it = blockIdx.x;               // global iteration index, stride NUM_CTAS
    if (it < n_iters) {
        const int b0 = it * ROWS_PER_ITER;
        ((float*)s[0][row])[off] = __ldg(x + (size_t)(b0 + row) * ROW_IN + off);
    }

    int buf = 0;
    for (; it < n_iters; it += NUM_CTAS, buf ^= 1) {
        __syncthreads();               // staged input for `it` ready in s[buf]

        // Prefetch next iteration's input into the other buffer.
        const int it_next = it + NUM_CTAS;
        if (it_next < n_iters) {
            const int bn = it_next * ROWS_PER_ITER;
            ((float*)s[buf ^ 1][row])[off] =
                __ldg(x + (size_t)(bn + row) * ROW_IN + off);
        }

        const int b0 = it * ROWS_PER_ITER;
        #pragma unroll
        for (int r = 0; r < ROWS_PER_ITER; ++r) {
            float4* __restrict__ o4 =
                reinterpret_cast<float4*>(out + (size_t)(b0 + r) * ROW_OUT);
            const float* __restrict__ sa = s[buf][r][0];
            const float* __restrict__ sb = s[buf][r][1];

            #pragma unroll
            for (int k = 0; k < 4; ++k) {
                const int idx = k * 1024 + tid * 4;   // linear output index
                const int j1  = idx >> 6;             // 0..63
                const int j2  = idx & 63;             // multiple of 4
                const float  av = sa[j1];
                const float4 bv = *reinterpret_cast<const float4*>(&sb[j2]);
                float4 v;
                v.x = av * bv.x;
                v.y = av * bv.y;
                v.z = av * bv.z;
                v.w = av * bv.w;
                __stcs(&o4[idx >> 2], v);             // streaming store
            }
        }
    }
}

extern "C" void kernel_launch(void* const* d_in, const int* in_sizes, int n_in,
                              void* d_out, int out_size) {
    const float* x = (const float*)d_in[0];
    float* out = (float*)d_out;
    const int batch = in_sizes[0] / ROW_IN;          // 32768
    const int n_iters = batch / ROWS_PER_ITER;       // 16384
    anfis_outer_persist_kernel<<<NUM_CTAS, 256>>>(x, out, n_iters);
}

// round 12
// speedup vs baseline: 1.1572x; 1.1572x over previous
#include <cuda_runtime.h>

// out[b, j1*64 + j2] = x[b, 0, j1] * x[b, 1, j2]
// x: [32768, 2, 64] f32, out: [32768, 4096] f32
// CHAMPION (R2): 2 batch rows per CTA; 256 threads; each thread writes
// 8x float4 (32 floats) via streaming (evict-first) STG.128 stores.
//
// Why this shape is the floor (evidence from R1-R7 ncu):
//  - Kernel is write-bound: 512 MB compulsory f32 output, ~6.7 TB/s achieved
//    pure-write stream (HBM3e write ceiling; 8 TB/s spec is read-biased).
//  - Store path is irrelevant (STG.128 ≈ TMA bulk ≫ STG.256): LTS/DRAM
//    path-independence confirmed.
//  - Persistent/grid-stride and coarser CTAs both regress (store MLP across
//    many independent CTAs beats barriered loops).

#define N_MF    64
#define ROW_IN  128   // 2 * 64 floats per batch row
#define ROW_OUT 4096
#define ROWS_PER_CTA 2

__global__ void __launch_bounds__(256, 8)
anfis_outer_kernel(const float* __restrict__ x, float* __restrict__ out) {
    const int b0  = blockIdx.x * ROWS_PER_CTA;
    const int tid = threadIdx.x;

    // [row][half][64]: half 0 = x[b,0,:], half 1 = x[b,1,:]
    __shared__ float s[ROWS_PER_CTA][2][N_MF];

    // Load 2*128 = 256 floats with 256 threads, one each (coalesced).
    {
        const int row = tid >> 7;           // 0..1
        const int off = tid & 127;          // 0..127
        ((float*)s[row])[off] = __ldg(x + (size_t)(b0 + row) * ROW_IN + off);
    }
    __syncthreads();

    #pragma unroll
    for (int r = 0; r < ROWS_PER_CTA; ++r) {
        float4* __restrict__ o4 =
            reinterpret_cast<float4*>(out + (size_t)(b0 + r) * ROW_OUT);
        const float* __restrict__ sa = s[r][0];
        const float* __restrict__ sb = s[r][1];

        #pragma unroll
        for (int k = 0; k < 4; ++k) {
            const int idx = k * 1024 + tid * 4;   // linear output index
            const int j1  = idx >> 6;             // 0..63
            const int j2  = idx & 63;             // multiple of 4
            const float  av = sa[j1];
            const float4 bv = *reinterpret_cast<const float4*>(&sb[j2]);
            float4 v;
            v.x = av * bv.x;
            v.y = av * bv.y;
            v.z = av * bv.z;
            v.w = av * bv.w;
            __stcs(&o4[idx >> 2], v);             // streaming: evict-first in L2
        }
    }
}

extern "C" void kernel_launch(void* const* d_in, const int* in_sizes, int n_in,
                              void* d_out, int out_size) {
    const float* x = (const float*)d_in[0];
    float* out = (float*)d_out;
    const int batch = in_sizes[0] / ROW_IN;          // 32768
    anfis_outer_kernel<<<batch / ROWS_PER_CTA, 256>>>(x, out);
}